// round 2
// baseline (speedup 1.0000x reference)
#include <cuda_runtime.h>
#include <cstdint>

// Problem constants (fixed by setup_inputs)
#define BATCH 16
#define NPTS  256
#define NHEAD 8
#define HID   64
#define NIN   12

#define PIX_PER_THREAD 2
#define TPB 128
#define MIN_BLOCKS 5   // caps regs at ~102 -> 5 CTAs/SM = 62.5% occ

// ---------------- packed f32x2 helpers ----------------
__device__ __forceinline__ unsigned long long pack2(float lo, float hi) {
    unsigned long long r;
    asm("mov.b64 %0, {%1, %2};" : "=l"(r) : "f"(lo), "f"(hi));
    return r;
}
__device__ __forceinline__ void unpack2(unsigned long long v, float& lo, float& hi) {
    asm("mov.b64 {%0, %1}, %2;" : "=f"(lo), "=f"(hi) : "l"(v));
}
__device__ __forceinline__ unsigned long long ffma2(unsigned long long a,
                                                    unsigned long long b,
                                                    unsigned long long c) {
    unsigned long long d;
    asm("fma.rn.f32x2 %0, %1, %2, %3;" : "=l"(d) : "l"(a), "l"(b), "l"(c));
    return d;
}

__device__ __forceinline__ float silu_f(float x) {
    return __fdividef(x, 1.0f + __expf(-x));   // MUFU.EX2 + MUFU.RCP
}

__device__ __forceinline__ void compute_features(float4 f, float* o) {
    float rx = f.x, ry = f.y, rvx = f.z, rvy = f.w;
    float d2    = fmaf(rx, rx, ry * ry);
    float dist  = __fsqrt_rn(d2 + 1e-6f);
    float invde = __fdividef(1.0f, dist + 1e-6f);
    float invd  = __fdividef(1.0f, dist + 0.1f);
    float ssq   = fmaf(rvx, rvx, rvy * rvy);
    float rsp   = __fsqrt_rn(ssq + 1e-6f);
    float dot   = fmaf(rvx, rx, rvy * ry);
    float closing = dot * invde;
    // tanh(a), a = -dot/(ssq+1e-6):  tanh(a) = 1 - 2/(exp(2a)+1)
    float a    = -__fdividef(dot, ssq + 1e-6f);
    float e2a  = __expf(2.0f * a);
    float ttca = 1.0f - __fdividef(2.0f, e2a + 1.0f);
    o[0]  = rx;       o[1]  = ry;       o[2]  = rvx;      o[3]  = rvy;
    o[4]  = dist;     o[5]  = invd;     o[6]  = rsp;      o[7]  = closing;
    o[8]  = rx * invde; o[9] = ry * invde; o[10] = ttca;  o[11] = dot;
}

__global__ void __launch_bounds__(TPB, MIN_BLOCKS)
relfeat_mlp_kernel(const float* __restrict__ ff,
                   const float* __restrict__ W1,
                   const float* __restrict__ b1,
                   const float* __restrict__ W2,
                   const float* __restrict__ b2,
                   float* __restrict__ out) {
    // Weights cached in shared, dup-packed into both f32x2 halves, and stored
    // TRANSPOSED so the inner loops walk consecutive u64s -> LDS.128 loads
    // two dup-weights per instruction.
    __shared__ unsigned long long sW1t[HID * NIN];   // [j][i], dup, 16B-aligned rows (12*8B)
    __shared__ unsigned long long sB1[HID];
    __shared__ unsigned long long sW2t[HID * NHEAD]; // [j][o], dup
    __shared__ unsigned long long sB2[NHEAD];

    for (int idx = threadIdx.x; idx < NIN * HID; idx += TPB) {
        int i = idx / HID, j = idx % HID;            // W1 is [i][j] row-major
        float w = W1[idx]; sW1t[j * NIN + i] = pack2(w, w);
    }
    for (int idx = threadIdx.x; idx < HID;       idx += TPB) { float w = b1[idx]; sB1[idx] = pack2(w, w); }
    for (int idx = threadIdx.x; idx < HID*NHEAD; idx += TPB) { float w = W2[idx]; sW2t[idx] = pack2(w, w); } // already [j][o]
    for (int idx = threadIdx.x; idx < NHEAD;     idx += TPB) { float w = b2[idx]; sB2[idx] = pack2(w, w); }
    __syncthreads();

    int t   = blockIdx.x * TPB + threadIdx.x;
    int pix = t * PIX_PER_THREAD;                  // linear pixel index (b*N+n)*N+m
    int m   = pix & (NPTS - 1);
    int n   = (pix >> 8) & (NPTS - 1);
    int b   = pix >> 16;

    const float4* ffp = reinterpret_cast<const float4*>(ff);
    float4 r0 = ffp[pix + 0];
    float4 r1 = ffp[pix + 1];

    float f0[NIN], f1[NIN];
    compute_features(r0, f0);
    compute_features(r1, f1);

    unsigned long long fA[NIN];
    #pragma unroll
    for (int i = 0; i < NIN; i++) fA[i] = pack2(f0[i], f1[i]);

    unsigned long long oA[NHEAD];
    #pragma unroll
    for (int o = 0; o < NHEAD; o++) oA[o] = sB2[o];

    const ulonglong2* w1v = reinterpret_cast<const ulonglong2*>(sW1t);
    const ulonglong2* w2v = reinterpret_cast<const ulonglong2*>(sW2t);

    #pragma unroll 4
    for (int j = 0; j < HID; j++) {
        unsigned long long acc = sB1[j];
        #pragma unroll
        for (int i2 = 0; i2 < NIN / 2; i2++) {       // LDS.128: two dup-weights
            ulonglong2 w = w1v[j * (NIN / 2) + i2];
            acc = ffma2(fA[2 * i2 + 0], w.x, acc);
            acc = ffma2(fA[2 * i2 + 1], w.y, acc);
        }
        float x0, x1;
        unpack2(acc, x0, x1);
        x0 = silu_f(x0); x1 = silu_f(x1);
        unsigned long long h = pack2(x0, x1);
        #pragma unroll
        for (int o2 = 0; o2 < NHEAD / 2; o2++) {     // LDS.128
            ulonglong2 w = w2v[j * (NHEAD / 2) + o2];
            oA[2 * o2 + 0] = ffma2(h, w.x, oA[2 * o2 + 0]);
            oA[2 * o2 + 1] = ffma2(h, w.y, oA[2 * o2 + 1]);
        }
    }

    // Output layout (B, H, N, N); 2 consecutive m -> one float2 store per head
    float2* outv = reinterpret_cast<float2*>(out);
    int base = (((b * NHEAD) * NPTS) + n) * (NPTS / 2) + (m >> 1);
    #pragma unroll
    for (int o = 0; o < NHEAD; o++) {
        float v0, v1;
        unpack2(oA[o], v0, v1);
        outv[base + o * NPTS * (NPTS / 2)] = make_float2(v0, v1);
    }
}

extern "C" void kernel_launch(void* const* d_in, const int* in_sizes, int n_in,
                              void* d_out, int out_size) {
    const float* ff = (const float*)d_in[0];
    const float* W1 = (const float*)d_in[1];
    const float* b1 = (const float*)d_in[2];
    const float* W2 = (const float*)d_in[3];
    const float* b2 = (const float*)d_in[4];
    float* out = (float*)d_out;

    int pixels  = out_size / NHEAD;                 // 1,048,576
    int threads = pixels / PIX_PER_THREAD;          // 524,288
    int blocks  = threads / TPB;                    // 4096
    relfeat_mlp_kernel<<<blocks, TPB>>>(ff, W1, b1, W2, b2, out);
}

// round 3
// speedup vs baseline: 1.1198x; 1.1198x over previous
#include <cuda_runtime.h>
#include <cstdint>

// Problem constants (fixed by setup_inputs)
#define BATCH 16
#define NPTS  256
#define NHEAD 8
#define HID   64
#define NIN   12

#define PIX_PER_THREAD 4
#define TPB 128
#define MIN_BLOCKS 4   // 128-reg budget -> 4 CTAs/SM (50% occ cap)

// ---------------- packed f32x2 helpers ----------------
__device__ __forceinline__ unsigned long long pack2(float lo, float hi) {
    unsigned long long r;
    asm("mov.b64 %0, {%1, %2};" : "=l"(r) : "f"(lo), "f"(hi));
    return r;
}
__device__ __forceinline__ void unpack2(unsigned long long v, float& lo, float& hi) {
    asm("mov.b64 {%0, %1}, %2;" : "=f"(lo), "=f"(hi) : "l"(v));
}
__device__ __forceinline__ unsigned long long ffma2(unsigned long long a,
                                                    unsigned long long b,
                                                    unsigned long long c) {
    unsigned long long d;
    asm("fma.rn.f32x2 %0, %1, %2, %3;" : "=l"(d) : "l"(a), "l"(b), "l"(c));
    return d;
}

__device__ __forceinline__ float silu_f(float x) {
    return __fdividef(x, 1.0f + __expf(-x));   // MUFU.EX2 + MUFU.RCP
}

__device__ __forceinline__ void compute_features(float4 f, float* o) {
    float rx = f.x, ry = f.y, rvx = f.z, rvy = f.w;
    float d2    = fmaf(rx, rx, ry * ry);
    float dist  = __fsqrt_rn(d2 + 1e-6f);
    float invde = __fdividef(1.0f, dist + 1e-6f);
    float invd  = __fdividef(1.0f, dist + 0.1f);
    float ssq   = fmaf(rvx, rvx, rvy * rvy);
    float rsp   = __fsqrt_rn(ssq + 1e-6f);
    float dot   = fmaf(rvx, rx, rvy * ry);
    float closing = dot * invde;
    // tanh(a), a = -dot/(ssq+1e-6):  tanh(a) = 1 - 2/(exp(2a)+1)
    float a    = -__fdividef(dot, ssq + 1e-6f);
    float e2a  = __expf(2.0f * a);
    float ttca = 1.0f - __fdividef(2.0f, e2a + 1.0f);
    o[0]  = rx;       o[1]  = ry;       o[2]  = rvx;      o[3]  = rvy;
    o[4]  = dist;     o[5]  = invd;     o[6]  = rsp;      o[7]  = closing;
    o[8]  = rx * invde; o[9] = ry * invde; o[10] = ttca;  o[11] = dot;
}

__global__ void __launch_bounds__(TPB, MIN_BLOCKS)
relfeat_mlp_kernel(const float* __restrict__ ff,
                   const float* __restrict__ W1,
                   const float* __restrict__ b1,
                   const float* __restrict__ W2,
                   const float* __restrict__ b2,
                   float* __restrict__ out) {
    // Weights in shared, dup-packed into both f32x2 halves, stored TRANSPOSED
    // so inner loops walk consecutive u64s -> LDS.128 loads two dup-weights
    // per instruction. All accesses are warp-uniform broadcasts.
    __shared__ unsigned long long sW1t[HID * NIN];   // [j][i], dup
    __shared__ unsigned long long sB1[HID];
    __shared__ unsigned long long sW2t[HID * NHEAD]; // [j][o], dup
    __shared__ unsigned long long sB2[NHEAD];

    for (int idx = threadIdx.x; idx < NIN * HID; idx += TPB) {
        int i = idx / HID, j = idx % HID;            // W1 is [i][j] row-major
        float w = W1[idx]; sW1t[j * NIN + i] = pack2(w, w);
    }
    for (int idx = threadIdx.x; idx < HID;       idx += TPB) { float w = b1[idx]; sB1[idx] = pack2(w, w); }
    for (int idx = threadIdx.x; idx < HID*NHEAD; idx += TPB) { float w = W2[idx]; sW2t[idx] = pack2(w, w); } // already [j][o]
    for (int idx = threadIdx.x; idx < NHEAD;     idx += TPB) { float w = b2[idx]; sB2[idx] = pack2(w, w); }
    __syncthreads();

    int t   = blockIdx.x * TPB + threadIdx.x;
    int pix = t * PIX_PER_THREAD;                  // linear pixel index (b*N+n)*N+m
    int m   = pix & (NPTS - 1);
    int n   = (pix >> 8) & (NPTS - 1);
    int b   = pix >> 16;

    const float4* ffp = reinterpret_cast<const float4*>(ff);

    // Pack features pixel-pair by pixel-pair; scalar temps scoped so the two
    // pairs' scalars are never simultaneously live (register pressure).
    unsigned long long fA[NIN], fB[NIN];
    {
        float4 r0 = ffp[pix + 0];
        float4 r1 = ffp[pix + 1];
        float f0[NIN], f1[NIN];
        compute_features(r0, f0);
        compute_features(r1, f1);
        #pragma unroll
        for (int i = 0; i < NIN; i++) fA[i] = pack2(f0[i], f1[i]);
    }
    {
        float4 r2 = ffp[pix + 2];
        float4 r3 = ffp[pix + 3];
        float f2[NIN], f3[NIN];
        compute_features(r2, f2);
        compute_features(r3, f3);
        #pragma unroll
        for (int i = 0; i < NIN; i++) fB[i] = pack2(f2[i], f3[i]);
    }

    unsigned long long oA[NHEAD], oB[NHEAD];
    #pragma unroll
    for (int o = 0; o < NHEAD; o++) { oA[o] = sB2[o]; oB[o] = sB2[o]; }

    const ulonglong2* w1v = reinterpret_cast<const ulonglong2*>(sW1t);
    const ulonglong2* w2v = reinterpret_cast<const ulonglong2*>(sW2t);

    #pragma unroll 2
    for (int j = 0; j < HID; j++) {
        unsigned long long accA = sB1[j];
        unsigned long long accB = accA;
        #pragma unroll
        for (int i2 = 0; i2 < NIN / 2; i2++) {       // LDS.128: two dup-weights
            ulonglong2 w = w1v[j * (NIN / 2) + i2];
            accA = ffma2(fA[2 * i2 + 0], w.x, accA);
            accB = ffma2(fB[2 * i2 + 0], w.x, accB);
            accA = ffma2(fA[2 * i2 + 1], w.y, accA);
            accB = ffma2(fB[2 * i2 + 1], w.y, accB);
        }
        float x0, x1, x2, x3;
        unpack2(accA, x0, x1);
        unpack2(accB, x2, x3);
        x0 = silu_f(x0); x1 = silu_f(x1); x2 = silu_f(x2); x3 = silu_f(x3);
        unsigned long long hA = pack2(x0, x1);
        unsigned long long hB = pack2(x2, x3);
        #pragma unroll
        for (int o2 = 0; o2 < NHEAD / 2; o2++) {     // LDS.128
            ulonglong2 w = w2v[j * (NHEAD / 2) + o2];
            oA[2 * o2 + 0] = ffma2(hA, w.x, oA[2 * o2 + 0]);
            oB[2 * o2 + 0] = ffma2(hB, w.x, oB[2 * o2 + 0]);
            oA[2 * o2 + 1] = ffma2(hA, w.y, oA[2 * o2 + 1]);
            oB[2 * o2 + 1] = ffma2(hB, w.y, oB[2 * o2 + 1]);
        }
    }

    // Output layout (B, H, N, N); 4 consecutive m -> one float4 store per head
    float4* outv = reinterpret_cast<float4*>(out);
    int base = (((b * NHEAD) * NPTS) + n) * (NPTS / 4) + (m >> 2);
    #pragma unroll
    for (int o = 0; o < NHEAD; o++) {
        float v0, v1, v2, v3;
        unpack2(oA[o], v0, v1);
        unpack2(oB[o], v2, v3);
        outv[base + o * NPTS * (NPTS / 4)] = make_float4(v0, v1, v2, v3);
    }
}

extern "C" void kernel_launch(void* const* d_in, const int* in_sizes, int n_in,
                              void* d_out, int out_size) {
    const float* ff = (const float*)d_in[0];
    const float* W1 = (const float*)d_in[1];
    const float* b1 = (const float*)d_in[2];
    const float* W2 = (const float*)d_in[3];
    const float* b2 = (const float*)d_in[4];
    float* out = (float*)d_out;

    int pixels  = out_size / NHEAD;                 // 1,048,576
    int threads = pixels / PIX_PER_THREAD;          // 262,144
    int blocks  = threads / TPB;                    // 2048
    relfeat_mlp_kernel<<<blocks, TPB>>>(ff, W1, b1, W2, b2, out);
}

// round 5
// speedup vs baseline: 1.6710x; 1.4923x over previous
#include <cuda_runtime.h>
#include <cstdint>

#define NPTS   256
#define NHEAD  8
#define HID    64
#define TPB    128
#define WARPS  4
#define TILES  4            // 32-pixel tiles per warp
#define CTA_PIX (WARPS * TILES * 32)   // 512

#define ROW_STRIDE 48       // bytes per staged pixel row (conflict-free for ldmatrix)
#define PLANE_BYTES (32 * ROW_STRIDE)
#define WARP_SMEM   (2 * PLANE_BYTES)  // hi + lo planes

__device__ __forceinline__ uint32_t smem_u32(const void* p) {
    uint32_t a;
    asm("{ .reg .u64 t; cvta.to.shared.u64 t, %1; cvt.u32.u64 %0, t; }" : "=r"(a) : "l"(p));
    return a;
}
__device__ __forceinline__ void ldm_x4(uint32_t* r, uint32_t addr) {
    asm volatile("ldmatrix.sync.aligned.m8n8.x4.shared.b16 {%0,%1,%2,%3}, [%4];"
                 : "=r"(r[0]), "=r"(r[1]), "=r"(r[2]), "=r"(r[3]) : "r"(addr));
}
__device__ __forceinline__ void mma_bf16(float* d, const uint32_t* a, const uint32_t* b) {
    asm volatile("mma.sync.aligned.m16n8k16.row.col.f32.bf16.bf16.f32 "
                 "{%0,%1,%2,%3}, {%4,%5,%6,%7}, {%8,%9}, {%0,%1,%2,%3};"
                 : "+f"(d[0]), "+f"(d[1]), "+f"(d[2]), "+f"(d[3])
                 : "r"(a[0]), "r"(a[1]), "r"(a[2]), "r"(a[3]), "r"(b[0]), "r"(b[1]));
}
// pack two f32 -> bf16x2 (v0 in LOW half), round-to-nearest
__device__ __forceinline__ uint32_t pack_rn(float v0, float v1) {
    uint32_t r;
    asm("cvt.rn.bf16x2.f32 %0, %1, %2;" : "=r"(r) : "f"(v1), "f"(v0));
    return r;
}
// hi = truncated bf16 pair (v0 low), lo = bf16_rn residual pair
__device__ __forceinline__ void split2(float v0, float v1, uint32_t& hi, uint32_t& lo) {
    uint32_t a = __float_as_uint(v0), b = __float_as_uint(v1);
    hi = __byte_perm(a, b, 0x7632);
    float l0 = v0 - __uint_as_float(a & 0xffff0000u);
    float l1 = v1 - __uint_as_float(b & 0xffff0000u);
    lo = pack_rn(l0, l1);
}

__device__ __forceinline__ float silu_f(float x) {
    return __fdividef(x, 1.0f + __expf(-x));   // MUFU.EX2 + MUFU.RCP
}

__device__ __forceinline__ void compute_features(float4 f, float* o) {
    float rx = f.x, ry = f.y, rvx = f.z, rvy = f.w;
    float d2    = fmaf(rx, rx, ry * ry);
    float dist  = __fsqrt_rn(d2 + 1e-6f);
    float invde = __fdividef(1.0f, dist + 1e-6f);
    float invd  = __fdividef(1.0f, dist + 0.1f);
    float ssq   = fmaf(rvx, rvx, rvy * rvy);
    float rsp   = __fsqrt_rn(ssq + 1e-6f);
    float dot   = fmaf(rvx, rx, rvy * ry);
    float closing = dot * invde;
    float a    = -__fdividef(dot, ssq + 1e-6f);
    float e2a  = __expf(2.0f * a);
    float ttca = 1.0f - __fdividef(2.0f, e2a + 1.0f);
    o[0]  = rx;       o[1]  = ry;       o[2]  = rvx;      o[3]  = rvy;
    o[4]  = dist;     o[5]  = invd;     o[6]  = rsp;      o[7]  = closing;
    o[8]  = rx * invde; o[9] = ry * invde; o[10] = ttca;  o[11] = dot;
}

__global__ void __launch_bounds__(TPB, 4)
relfeat_hmma_kernel(const float* __restrict__ ff,
                    const float* __restrict__ W1,
                    const float* __restrict__ b1,
                    const float* __restrict__ W2,
                    const float* __restrict__ b2,
                    float* __restrict__ out) {
    __shared__ __align__(16) char stage[WARPS * WARP_SMEM];

    const int tid  = threadIdx.x;
    const int wid  = tid >> 5;
    const int lane = tid & 31;
    const int q    = lane & 3;        // quad col index
    const int g    = lane >> 2;       // row group

    const uint32_t hiBase = smem_u32(stage) + wid * WARP_SMEM;
    const uint32_t loBase = hiBase + PLANE_BYTES;

    // ---------- weights -> registers (per-warp, broadcast LDG) ----------
    // Layer1 B fragments: B1[k][n], k: 0..11 = W1 rows, 12 = b1, 13..15 = 0
    uint32_t w1hi[8][2], w1lo[8][2];
    {
        int n = (wid, g);  // silence unused
        (void)n;
    }
    #pragma unroll
    for (int t = 0; t < 8; t++) {
        int n = t * 8 + g;
        int k0 = 2 * q, k2 = 2 * q + 8;
        float v0 = W1[k0 * HID + n];
        float v1 = W1[(k0 + 1) * HID + n];
        float v2 = (k2 < 12) ? W1[k2 * HID + n] : (k2 == 12 ? b1[n] : 0.0f);
        float v3 = (k2 + 1 < 12) ? W1[(k2 + 1) * HID + n] : (k2 + 1 == 12 ? b1[n] : 0.0f);
        split2(v0, v1, w1hi[t][0], w1lo[t][0]);
        split2(v2, v3, w1hi[t][1], w1lo[t][1]);
    }
    // Layer2 B fragments: B2[k][o] = W2[k*8+o], k = 0..63
    uint32_t w2hi[4][2], w2lo[4][2];
    #pragma unroll
    for (int kt = 0; kt < 4; kt++) {
        int o = g;
        int k0 = 16 * kt + 2 * q;
        float v0 = W2[k0 * NHEAD + o];
        float v1 = W2[(k0 + 1) * NHEAD + o];
        float v2 = W2[(k0 + 8) * NHEAD + o];
        float v3 = W2[(k0 + 9) * NHEAD + o];
        split2(v0, v1, w2hi[kt][0], w2lo[kt][0]);
        split2(v2, v3, w2hi[kt][1], w2lo[kt][1]);
    }
    float b2a = b2[2 * q], b2b = b2[2 * q + 1];

    const int gw = blockIdx.x * WARPS + wid;   // global warp id
    const float4* ffp = reinterpret_cast<const float4*>(ff);

    // ldmatrix row address for this lane (within a 16-row mtile)
    const int lt = lane >> 3, lr = lane & 7;
    const uint32_t ldmOff = (uint32_t)(((lt & 1) * 8 + lr) * ROW_STRIDE + (lt >> 1) * 16);

    #pragma unroll 1
    for (int it = 0; it < TILES; it++) {
        const int pixBase = gw * (TILES * 32) + it * 32;

        // ---- features for this lane's pixel -> hi/lo bf16 rows in SMEM ----
        {
            float4 raw = ffp[pixBase + lane];
            float f[12];
            compute_features(raw, f);
            uint32_t hi8[8], lo8[8];
            #pragma unroll
            for (int c = 0; c < 6; c++) split2(f[2 * c], f[2 * c + 1], hi8[c], lo8[c]);
            hi8[6] = 0x00003F80u; lo8[6] = 0;   // k=12: 1.0 (bias lane), k=13: 0
            hi8[7] = 0;           lo8[7] = 0;   // k=14,15
            __syncwarp();
            uint32_t row = (uint32_t)lane * ROW_STRIDE;
            *reinterpret_cast<uint4*>(stage + (hiBase - smem_u32(stage)) + row)      = make_uint4(hi8[0], hi8[1], hi8[2], hi8[3]);
            *reinterpret_cast<uint4*>(stage + (hiBase - smem_u32(stage)) + row + 16) = make_uint4(hi8[4], hi8[5], hi8[6], hi8[7]);
            *reinterpret_cast<uint4*>(stage + (loBase - smem_u32(stage)) + row)      = make_uint4(lo8[0], lo8[1], lo8[2], lo8[3]);
            *reinterpret_cast<uint4*>(stage + (loBase - smem_u32(stage)) + row + 16) = make_uint4(lo8[4], lo8[5], lo8[6], lo8[7]);
            __syncwarp();
        }

        #pragma unroll
        for (int mt = 0; mt < 2; mt++) {
            // ---- A fragments via ldmatrix ----
            uint32_t ahi[4], alo[4];
            ldm_x4(ahi, hiBase + (uint32_t)(mt * 16 * ROW_STRIDE) + ldmOff);
            ldm_x4(alo, loBase + (uint32_t)(mt * 16 * ROW_STRIDE) + ldmOff);

            // ---- layer1: D1 = A*B1 (3-product split) ----
            float d[8][4];
            #pragma unroll
            for (int t = 0; t < 8; t++) {
                d[t][0] = d[t][1] = d[t][2] = d[t][3] = 0.0f;
                mma_bf16(d[t], ahi, w1hi[t]);
                mma_bf16(d[t], ahi, w1lo[t]);
                mma_bf16(d[t], alo, w1hi[t]);
            }
            // ---- SiLU in-register ----
            #pragma unroll
            for (int t = 0; t < 8; t++) {
                d[t][0] = silu_f(d[t][0]); d[t][1] = silu_f(d[t][1]);
                d[t][2] = silu_f(d[t][2]); d[t][3] = silu_f(d[t][3]);
            }
            // ---- layer2: accum layout == A-frag layout; split & MMA ----
            float dd[4] = {0.0f, 0.0f, 0.0f, 0.0f};
            #pragma unroll
            for (int kt = 0; kt < 4; kt++) {
                uint32_t a2hi[4], a2lo[4];
                split2(d[2 * kt][0],     d[2 * kt][1],     a2hi[0], a2lo[0]);
                split2(d[2 * kt][2],     d[2 * kt][3],     a2hi[1], a2lo[1]);
                split2(d[2 * kt + 1][0], d[2 * kt + 1][1], a2hi[2], a2lo[2]);
                split2(d[2 * kt + 1][2], d[2 * kt + 1][3], a2hi[3], a2lo[3]);
                mma_bf16(dd, a2hi, w2hi[kt]);
                mma_bf16(dd, a2hi, w2lo[kt]);
                mma_bf16(dd, a2lo, w2hi[kt]);
            }
            // ---- store transposed (B, H, N, N) ----
            int p0 = pixBase + mt * 16;
            int m = p0 & (NPTS - 1);
            int n = (p0 >> 8) & (NPTS - 1);
            int b = p0 >> 16;
            int base = b * (NHEAD * NPTS * NPTS) + n * NPTS + m;
            int c0 = (2 * q) * (NPTS * NPTS), c1 = (2 * q + 1) * (NPTS * NPTS);
            out[base + c0 + g]     = dd[0] + b2a;
            out[base + c1 + g]     = dd[1] + b2b;
            out[base + c0 + g + 8] = dd[2] + b2a;
            out[base + c1 + g + 8] = dd[3] + b2b;
        }
    }
}

extern "C" void kernel_launch(void* const* d_in, const int* in_sizes, int n_in,
                              void* d_out, int out_size) {
    const float* ff = (const float*)d_in[0];
    const float* W1 = (const float*)d_in[1];
    const float* b1 = (const float*)d_in[2];
    const float* W2 = (const float*)d_in[3];
    const float* b2 = (const float*)d_in[4];
    float* out = (float*)d_out;

    int pixels = out_size / NHEAD;        // 1,048,576
    int blocks = pixels / CTA_PIX;        // 2048
    relfeat_hmma_kernel<<<blocks, TPB>>>(ff, W1, b1, W2, b2, out);
}